// round 4
// baseline (speedup 1.0000x reference)
#include <cuda_runtime.h>
#include <cuda_bf16.h>

#define BB 32
#define CC 32
#define HH 480
#define WW 480
#define LL 120
#define HALF 60
#define PLANE (HH*WW)
#define RB 60            // reduce blocks per batch (8 rows each)

// per-(batch, reduce-block) partials: [cnt, sum_y, sum_x].
// Fully rewritten every replay before being read -> no zero-init, no atomics.
__device__ float g_part[BB * RB * 3];

// ---------------------------------------------------------------------------
// Kernel 1: masked centroid partials over channel-1 plane.
// Grid (RB, BB), block 256 (8 warps). Warp w owns row blockIdx.x*8 + w.
// Channel 1 is exactly {0.0, 1.0}, so mask == value: branch-free FMA stream.
// ---------------------------------------------------------------------------
__global__ void __launch_bounds__(256) reduce_pos_kernel(const float* __restrict__ in) {
    const int b    = blockIdx.y;
    const int w    = threadIdx.x >> 5;
    const int lane = threadIdx.x & 31;
    const int y    = blockIdx.x * 8 + w;

    const float4* __restrict__ row =
        (const float4*)(in + (size_t)b * CC * PLANE + (size_t)PLANE + (size_t)y * WW);

    float c = 0.0f, sx = 0.0f;
    #pragma unroll
    for (int k = 0; k < 4; k++) {
        const int xi = lane + 32 * k;          // float4 index in row, 120 per row
        if (xi < WW / 4) {
            float4 v  = row[xi];
            float  s4 = (v.x + v.y) + (v.z + v.w);
            c  += s4;
            sx += (float)(4 * xi) * s4 + (v.y + 2.0f * v.z + 3.0f * v.w);
        }
    }
    float sy = (float)y * c;                   // row constant per warp

    #pragma unroll
    for (int o = 16; o > 0; o >>= 1) {
        c  += __shfl_down_sync(0xffffffffu, c,  o);
        sy += __shfl_down_sync(0xffffffffu, sy, o);
        sx += __shfl_down_sync(0xffffffffu, sx, o);
    }
    __shared__ float s[3][8];
    if (lane == 0) { s[0][w] = c; s[1][w] = sy; s[2][w] = sx; }
    __syncthreads();
    if (threadIdx.x == 0) {
        float cc = 0.0f, ay = 0.0f, ax = 0.0f;
        #pragma unroll
        for (int i = 0; i < 8; i++) { cc += s[0][i]; ay += s[1][i]; ax += s[2][i]; }
        float* p = &g_part[(b * RB + blockIdx.x) * 3];
        p[0] = cc; p[1] = ay; p[2] = ax;
    }
}

// ---------------------------------------------------------------------------
// Kernel 2: crop + bilinear resize with small-tile smem staging.
// Grid (LL/4, CC/4, BB), block (128, 4) = 512 threads.
// Block handles (b, 4 channels, 4 output rows). fy <= 1 means those 4 output
// rows touch at most 5 source rows -> stage 5 rows x 4 ch x <=120 cols (10 KB)
// with fully coalesced loads, then conflict-free LDS for the bilinear taps.
// Warp 0 redundantly finalizes the crop window from the 60 partials (L2-hot).
// ---------------------------------------------------------------------------
__global__ void __launch_bounds__(512) crop_resize_kernel(
        const float* __restrict__ in, float* __restrict__ out) {
    const int b  = blockIdx.z;
    const int c0 = blockIdx.y * 4;

    __shared__ float tile[5 * 4 * 128];   // [row][ch][x]
    __shared__ int   swin[4];             // ys, ry, xs, rx
    __shared__ float sfac[2];             // fy, fx

    const int tid = threadIdx.y * 128 + threadIdx.x;

    if (tid < 32) {
        const int lane = tid;
        float c = 0.0f, sy = 0.0f, sx = 0.0f;
        if (lane < RB / 2) {
            const float* p = &g_part[(b * RB + lane) * 3];
            const float* q = &g_part[(b * RB + lane + RB / 2) * 3];
            c  = p[0] + q[0];
            sy = p[1] + q[1];
            sx = p[2] + q[2];
        }
        #pragma unroll
        for (int o = 16; o > 0; o >>= 1) {
            c  += __shfl_down_sync(0xffffffffu, c,  o);
            sy += __shfl_down_sync(0xffffffffu, sy, o);
            sx += __shfl_down_sync(0xffffffffu, sx, o);
        }
        if (lane == 0) {
            float denom = fmaxf(c, 1.0f);
            // rintf = round-half-even, matching jnp.round
            int py = (c > 0.0f) ? (int)rintf(sy / denom) : (HH / 2);
            int px = (c > 0.0f) ? (int)rintf(sx / denom) : (WW / 2);
            int ys = max(py - HALF, 0);
            int ry = min(py + HALF, HH) - ys;
            int xs = max(px - HALF, 0);
            int rx = min(px + HALF, WW) - xs;
            swin[0] = ys; swin[1] = ry; swin[2] = xs; swin[3] = rx;
            sfac[0] = (float)ry / (float)LL;
            sfac[1] = (float)rx / (float)LL;
        }
    }
    __syncthreads();

    const int   ys = swin[0], ry = swin[1], xs = swin[2], rx = swin[3];
    const float fy = sfac[0], fx = sfac[1];

    // first source row needed by this block's 4 output rows
    const int a = (int)fmaxf(((float)(blockIdx.x * 4) + 0.5f) * fy - 0.5f, 0.0f);

    const float* __restrict__ img = in + ((size_t)b * CC + c0) * PLANE;

    // stage: 5 rows x 4 ch x rx cols, coalesced (consecutive tid -> consecutive x)
    #pragma unroll
    for (int it = 0; it < 5; it++) {
        int i  = tid + it * 512;          // 0 .. 2559
        int x  = i & 127;
        int rc = i >> 7;                  // 0..19
        int ch = rc & 3;
        int r  = rc >> 2;                 // 0..4
        if (x < rx) {
            int srow = min(a + r, ry - 1);
            tile[i] = img[(size_t)ch * PLANE + (ys + srow) * WW + xs + x];
        }
    }
    __syncthreads();

    const int ox = threadIdx.x;
    if (ox >= LL) return;
    const int oy = blockIdx.x * 4 + threadIdx.y;

    float syv = fmaxf(((float)oy + 0.5f) * fy - 0.5f, 0.0f);
    float sxv = fmaxf(((float)ox + 0.5f) * fx - 0.5f, 0.0f);
    int y0 = (int)syv;                   // >= 0 -> trunc == floor
    int x0 = (int)sxv;
    int x1 = min(x0 + 1, rx - 1);
    float wy = syv - (float)y0;
    float wx = sxv - (float)x0;

    const int iy0 = y0 - a;                              // 0..3
    const int iy1 = min(y0 + 1, ry - 1) - a;             // 0..4

    float* __restrict__ obase =
        out + (((size_t)(b * CC + c0)) * LL + oy) * LL + ox;

    #pragma unroll
    for (int ch = 0; ch < 4; ch++) {
        const float* r0 = tile + (iy0 * 4 + ch) * 128;
        const float* r1 = tile + (iy1 * 4 + ch) * 128;
        float v00 = r0[x0], v01 = r0[x1];
        float v10 = r1[x0], v11 = r1[x1];
        float top = v00 * (1.0f - wx) + v01 * wx;
        float bot = v10 * (1.0f - wx) + v11 * wx;
        obase[(size_t)ch * (LL * LL)] = top * (1.0f - wy) + bot * wy;
    }
}

extern "C" void kernel_launch(void* const* d_in, const int* in_sizes, int n_in,
                              void* d_out, int out_size) {
    const float* in = (const float*)d_in[0];
    float* out = (float*)d_out;

    reduce_pos_kernel<<<dim3(RB, BB), 256>>>(in);

    dim3 cb(128, 4);                    // 512 threads
    dim3 cg(LL / 4, CC / 4, BB);        // 30 x 8 x 32 = 7680 blocks
    crop_resize_kernel<<<cg, cb>>>(in, out);
}

// round 5
// speedup vs baseline: 1.1580x; 1.1580x over previous
#include <cuda_runtime.h>
#include <cuda_bf16.h>

#define BB 32
#define CC 32
#define HH 480
#define WW 480
#define LL 120
#define HALF 60
#define PLANE (HH*WW)
#define RB 60            // reduce blocks per batch (8 rows each)

// per-(batch, reduce-block) partials: [cnt, sum_y, sum_x].
// Fully rewritten every replay before being read -> no zero-init, no atomics.
__device__ float g_part[BB * RB * 3];

// ---------------------------------------------------------------------------
// Kernel 1: masked centroid partials over channel-1 plane.
// Grid (RB, BB), block 256 (8 warps). Warp w owns row blockIdx.x*8 + w.
// Channel 1 is exactly {0.0, 1.0}, so mask == value: branch-free FMA stream.
// ---------------------------------------------------------------------------
__global__ void __launch_bounds__(256) reduce_pos_kernel(const float* __restrict__ in) {
    const int b    = blockIdx.y;
    const int w    = threadIdx.x >> 5;
    const int lane = threadIdx.x & 31;
    const int y    = blockIdx.x * 8 + w;

    const float4* __restrict__ row =
        (const float4*)(in + (size_t)b * CC * PLANE + (size_t)PLANE + (size_t)y * WW);

    float c = 0.0f, sx = 0.0f;
    #pragma unroll
    for (int k = 0; k < 4; k++) {
        const int xi = lane + 32 * k;          // float4 index in row, 120 per row
        if (xi < WW / 4) {
            float4 v  = row[xi];
            float  s4 = (v.x + v.y) + (v.z + v.w);
            c  += s4;
            sx += (float)(4 * xi) * s4 + (v.y + 2.0f * v.z + 3.0f * v.w);
        }
    }
    float sy = (float)y * c;                   // row constant per warp

    #pragma unroll
    for (int o = 16; o > 0; o >>= 1) {
        c  += __shfl_down_sync(0xffffffffu, c,  o);
        sy += __shfl_down_sync(0xffffffffu, sy, o);
        sx += __shfl_down_sync(0xffffffffu, sx, o);
    }
    __shared__ float s[3][8];
    if (lane == 0) { s[0][w] = c; s[1][w] = sy; s[2][w] = sx; }
    __syncthreads();
    if (threadIdx.x == 0) {
        float cc = 0.0f, ay = 0.0f, ax = 0.0f;
        #pragma unroll
        for (int i = 0; i < 8; i++) { cc += s[0][i]; ay += s[1][i]; ax += s[2][i]; }
        float* p = &g_part[(b * RB + blockIdx.x) * 3];
        p[0] = cc; p[1] = ay; p[2] = ax;
    }
}

// ---------------------------------------------------------------------------
// Kernel 2: crop + bilinear resize.
// Grid (LL/4, CC/4, BB), block (128, 4) = 512 threads. Block = (b, 4 ch, 4 rows).
//
// Fast path (ry==rx==120, i.e. unclamped window): the resize is an exact
// identity -> pure 120x120 crop copy. Warp = (channel, row); lane moves 4
// consecutive x with one float4 STG (and float4 LDG when the crop is 16B
// aligned). ~29/32 batches take this path.
//
// Slow path (clamped windows): per-pixel 4-tap gather reusing weights across
// 4 channels (R3 structure).
// Warp 0 redundantly finalizes the crop window from the 60 partials (L2-hot).
// ---------------------------------------------------------------------------
__global__ void __launch_bounds__(512) crop_resize_kernel(
        const float* __restrict__ in, float* __restrict__ out) {
    const int b  = blockIdx.z;
    const int c0 = blockIdx.y * 4;

    __shared__ int   swin[4];    // ys, ry, xs, rx
    __shared__ float sfac[2];    // fy, fx

    const int tid = threadIdx.y * 128 + threadIdx.x;
    if (tid < 32) {
        const int lane = tid;
        float c = 0.0f, sy = 0.0f, sx = 0.0f;
        if (lane < RB / 2) {
            const float* p = &g_part[(b * RB + lane) * 3];
            const float* q = &g_part[(b * RB + lane + RB / 2) * 3];
            c  = p[0] + q[0];
            sy = p[1] + q[1];
            sx = p[2] + q[2];
        }
        #pragma unroll
        for (int o = 16; o > 0; o >>= 1) {
            c  += __shfl_down_sync(0xffffffffu, c,  o);
            sy += __shfl_down_sync(0xffffffffu, sy, o);
            sx += __shfl_down_sync(0xffffffffu, sx, o);
        }
        if (lane == 0) {
            float denom = fmaxf(c, 1.0f);
            // rintf = round-half-even, matching jnp.round
            int py = (c > 0.0f) ? (int)rintf(sy / denom) : (HH / 2);
            int px = (c > 0.0f) ? (int)rintf(sx / denom) : (WW / 2);
            int ys = max(py - HALF, 0);
            int ry = min(py + HALF, HH) - ys;
            int xs = max(px - HALF, 0);
            int rx = min(px + HALF, WW) - xs;
            swin[0] = ys; swin[1] = ry; swin[2] = xs; swin[3] = rx;
            sfac[0] = (float)ry / (float)LL;
            sfac[1] = (float)rx / (float)LL;
        }
    }
    __syncthreads();

    const int ys = swin[0], ry = swin[1], xs = swin[2], rx = swin[3];

    if (ry == LL && rx == LL) {
        // ---------------- fast path: exact crop copy ----------------
        // warp w of 16: ch = w & 3, row = blockIdx.x*4 + (w >> 2)
        const int w    = tid >> 5;
        const int lane = tid & 31;
        if (lane >= LL / 4) return;          // 30 active lanes
        const int ch = w & 3;
        const int oy = blockIdx.x * 4 + (w >> 2);
        const int ox = lane * 4;

        const float* __restrict__ src =
            in + ((size_t)b * CC + c0 + ch) * PLANE + (size_t)(ys + oy) * WW + xs + ox;
        float4 v;
        if ((xs & 3) == 0) {
            v = *(const float4*)src;
        } else {
            v.x = src[0]; v.y = src[1]; v.z = src[2]; v.w = src[3];
        }
        *(float4*)(out + (((size_t)(b * CC + c0 + ch)) * LL + oy) * LL + ox) = v;
        return;
    }

    // ---------------- slow path: bilinear gather ----------------
    const float fy = sfac[0], fx = sfac[1];
    const int ox = threadIdx.x;
    if (ox >= LL) return;
    const int oy = blockIdx.x * 4 + threadIdx.y;

    float syv = fmaxf(((float)oy + 0.5f) * fy - 0.5f, 0.0f);
    float sxv = fmaxf(((float)ox + 0.5f) * fx - 0.5f, 0.0f);
    int y0 = (int)syv;                  // >= 0 -> trunc == floor
    int x0 = (int)sxv;
    int y1 = min(y0 + 1, ry - 1);
    int x1 = min(x0 + 1, rx - 1);
    float wy = syv - (float)y0;
    float wx = sxv - (float)x0;

    const int o00 = (ys + y0) * WW + xs + x0;
    const int o01 = (ys + y0) * WW + xs + x1;
    const int o10 = (ys + y1) * WW + xs + x0;
    const int o11 = (ys + y1) * WW + xs + x1;

    const float* __restrict__ img = in + ((size_t)b * CC + c0) * PLANE;
    float* __restrict__ obase =
        out + (((size_t)(b * CC + c0)) * LL + oy) * LL + ox;

    float v00[4], v01[4], v10[4], v11[4];
    #pragma unroll
    for (int ch = 0; ch < 4; ch++) {
        const float* __restrict__ p = img + (size_t)ch * PLANE;
        v00[ch] = p[o00];
        v01[ch] = p[o01];
        v10[ch] = p[o10];
        v11[ch] = p[o11];
    }
    #pragma unroll
    for (int ch = 0; ch < 4; ch++) {
        float top = v00[ch] * (1.0f - wx) + v01[ch] * wx;
        float bot = v10[ch] * (1.0f - wx) + v11[ch] * wx;
        obase[(size_t)ch * (LL * LL)] = top * (1.0f - wy) + bot * wy;
    }
}

extern "C" void kernel_launch(void* const* d_in, const int* in_sizes, int n_in,
                              void* d_out, int out_size) {
    const float* in = (const float*)d_in[0];
    float* out = (float*)d_out;

    reduce_pos_kernel<<<dim3(RB, BB), 256>>>(in);

    dim3 cb(128, 4);                    // 512 threads
    dim3 cg(LL / 4, CC / 4, BB);        // 30 x 8 x 32 = 7680 blocks
    crop_resize_kernel<<<cg, cb>>>(in, out);
}